// round 4
// baseline (speedup 1.0000x reference)
#include <cuda_runtime.h>

#define BATCH 32
#define SEQ   512
#define HID   256
#define TMEL  2000
#define H4    (HID / 4)      // 64 float4 per row
#define N4TOT (BATCH * TMEL * H4)   // 4,096,000 float4 outputs

// Scratch: per-position source-row index (computed by kernel A).
__device__ int g_idx[BATCH * TMEL];

// ---------------- Kernel A: scan + searchsorted + mel_len -------------------
__global__ __launch_bounds__(256)
void idx_kernel(const int* __restrict__ duration,
                float* __restrict__ out, int out_size) {
    const int b   = blockIdx.x;
    const int tid = threadIdx.x;
    const int wid   = tid >> 5;
    const int lane5 = tid & 31;

    __shared__ int csum[SEQ];
    __shared__ int wsum[8];

    // Each thread owns a pair of durations.
    const int2* dur2 = (const int2*)(duration + b * SEQ);
    int2 d = dur2[tid];
    int sc = d.x + d.y;
    #pragma unroll
    for (int off = 1; off < 32; off <<= 1) {
        int v = __shfl_up_sync(0xffffffffu, sc, off);
        if (lane5 >= off) sc += v;
    }
    if (lane5 == 31) wsum[wid] = sc;
    __syncthreads();
    int wprefix = 0;
    #pragma unroll
    for (int w = 0; w < 8; w++)
        wprefix += (w < wid) ? wsum[w] : 0;
    int inc_hi = sc + wprefix;
    csum[2 * tid]     = inc_hi - d.y;
    csum[2 * tid + 1] = inc_hi;
    __syncthreads();

    // searchsorted(cumsum, pos, side='right'), clipped to SEQ-1.
    // 8 positions per thread (256*8 = 2048 >= 2000), coalesced writes.
    #pragma unroll
    for (int i = 0; i < 8; i++) {
        int pos = tid + i * 256;
        if (pos < TMEL) {
            int lo = 0, hi = SEQ;
            while (lo < hi) {
                int mid = (lo + hi) >> 1;
                if (csum[mid] <= pos) lo = mid + 1; else hi = mid;
            }
            g_idx[b * TMEL + pos] = min(lo, SEQ - 1);
        }
    }

    // mel_len appended after the main output (if buffer includes it).
    if (tid == 255) {
        const int main_elems = BATCH * TMEL * HID;
        if (out_size >= main_elems + BATCH)
            out[main_elems + b] = (float)min(inc_hi, TMEL);
    }
}

// ---------------- Kernel B: pure streaming gather-copy ----------------------
// 2000 CTAs x 256 threads, 8 float4 per thread, grid-strided so every
// warp's accesses stay fully coalesced. All idx loads batched, then all
// x loads batched (MLP=8), then all stores.
#define ITEMS 8
#define TOTTHR (N4TOT / ITEMS)     // 512,000 threads

__global__ __launch_bounds__(256)
void copy_kernel(const float4* __restrict__ x4, float4* __restrict__ out4) {
    const int gtid = blockIdx.x * 256 + threadIdx.x;

    int n[ITEMS], src[ITEMS];
    #pragma unroll
    for (int k = 0; k < ITEMS; k++)
        n[k] = gtid + k * TOTTHR;

    // Batch 1: index lookups (L1/L2-hit, >=2 distinct per warp, broadcast).
    #pragma unroll
    for (int k = 0; k < ITEMS; k++)
        src[k] = __ldg(&g_idx[n[k] >> 6]);

    // Batch 2: gather loads (front-batched -> 8 in flight per thread).
    float4 v[ITEMS];
    #pragma unroll
    for (int k = 0; k < ITEMS; k++) {
        int row = n[k] >> 6;          // b*TMEL + t
        int b   = row / TMEL;
        int lane = n[k] & (H4 - 1);
        v[k] = __ldg(&x4[(b * SEQ + src[k]) * H4 + lane]);
    }

    // Batch 3: coalesced stores.
    #pragma unroll
    for (int k = 0; k < ITEMS; k++)
        out4[n[k]] = v[k];
}

extern "C" void kernel_launch(void* const* d_in, const int* in_sizes, int n_in,
                              void* d_out, int out_size) {
    const float* x        = (const float*)d_in[0];
    const int*   duration = (const int*)d_in[1];
    float*       out      = (float*)d_out;

    idx_kernel<<<BATCH, 256>>>(duration, out, out_size);
    copy_kernel<<<TOTTHR / 256, 256>>>((const float4*)x, (float4*)out);
}

// round 5
// speedup vs baseline: 1.0296x; 1.0296x over previous
#include <cuda_runtime.h>

#define BATCH 32
#define SEQ   512
#define HID   256
#define TMEL  2000
#define T_TILE 64
#define H4    (HID / 4)   // 64 float4 per row

__global__ __launch_bounds__(256)
void length_regulator_kernel(const float* __restrict__ x,
                             const int* __restrict__ duration,
                             float* __restrict__ out,
                             int out_size) {
    const int b   = blockIdx.y;
    const int t0  = blockIdx.x * T_TILE;
    const int tid = threadIdx.x;
    const int wid   = tid >> 5;
    const int lane5 = tid & 31;

    __shared__ int csum[SEQ];
    __shared__ int wsum[8];
    __shared__ int idxs[T_TILE];

    // ---- Prologue 1: shuffle-based inclusive scan (2 barriers total). ----
    const int2* dur2 = (const int2*)(duration + b * SEQ);
    int2 d = dur2[tid];
    int sc = d.x + d.y;
    #pragma unroll
    for (int off = 1; off < 32; off <<= 1) {
        int v = __shfl_up_sync(0xffffffffu, sc, off);
        if (lane5 >= off) sc += v;
    }
    if (lane5 == 31) wsum[wid] = sc;
    __syncthreads();
    int wprefix = 0;
    #pragma unroll
    for (int w = 0; w < 8; w++)
        wprefix += (w < wid) ? wsum[w] : 0;
    int inc_hi = sc + wprefix;            // inclusive cumsum at elem 2*tid+1
    csum[2 * tid]     = inc_hi - d.y;
    csum[2 * tid + 1] = inc_hi;
    __syncthreads();

    // ---- Prologue 2: searchsorted(cumsum, pos, 'right'), clip to SEQ-1. ----
    if (tid < T_TILE) {
        int pos = t0 + tid;               // pos >= TMEL still yields valid clamp
        int lo = 0, hi = SEQ;
        while (lo < hi) {
            int mid = (lo + hi) >> 1;
            if (csum[mid] <= pos) lo = mid + 1; else hi = mid;
        }
        idxs[tid] = min(lo, SEQ - 1);
    }
    __syncthreads();

    // ---- Copy: 64 threads per row (64 float4 = 1KB), 16 rows per thread,
    //      processed as 2 batches of 8 with all loads front-batched (MLP=8).
    const float4* __restrict__ xb = (const float4*)x + (b * SEQ) * H4;
    float4* __restrict__ ob = (float4*)out + (b * TMEL + t0) * H4;
    const int lane = tid & 63;    // float4 index within row
    const int rsub = tid >> 6;    // 0..3

    #pragma unroll
    for (int g = 0; g < 2; g++) {
        int srcs[8];
        #pragma unroll
        for (int k = 0; k < 8; k++)
            srcs[k] = idxs[rsub + 4 * (g * 8 + k)];

        float4 v[8];
        #pragma unroll
        for (int k = 0; k < 8; k++)
            v[k] = __ldg(&xb[srcs[k] * H4 + lane]);

        #pragma unroll
        for (int k = 0; k < 8; k++) {
            int r = rsub + 4 * (g * 8 + k);
            if (t0 + r < TMEL)
                ob[r * H4 + lane] = v[k];
        }
    }

    // ---- mel_len appended after main output (if buffer includes it). ----
    if (blockIdx.x == 0 && tid == 255) {
        const int main_elems = BATCH * TMEL * HID;
        if (out_size >= main_elems + BATCH)
            out[main_elems + b] = (float)min(inc_hi, TMEL);
    }
}

extern "C" void kernel_launch(void* const* d_in, const int* in_sizes, int n_in,
                              void* d_out, int out_size) {
    const float* x        = (const float*)d_in[0];
    const int*   duration = (const int*)d_in[1];
    float*       out      = (float*)d_out;

    dim3 grid((TMEL + T_TILE - 1) / T_TILE, BATCH);  // (32, 32)
    length_regulator_kernel<<<grid, 256>>>(x, duration, out, out_size);
}

// round 6
// speedup vs baseline: 1.1844x; 1.1503x over previous
#include <cuda_runtime.h>

#define BATCH 32
#define SEQ   512
#define HID   256
#define TMEL  2000
#define T_TILE 64
#define H4    (HID / 4)   // 64 float4 per row

__global__ __launch_bounds__(256, 8)   // cap regs at 32 -> occupancy ~8 CTA/SM
void length_regulator_kernel(const float* __restrict__ x,
                             const int* __restrict__ duration,
                             float* __restrict__ out,
                             int out_size) {
    const int b   = blockIdx.y;
    const int t0  = blockIdx.x * T_TILE;
    const int tid = threadIdx.x;
    const int wid   = tid >> 5;
    const int lane5 = tid & 31;

    __shared__ int csum[SEQ];
    __shared__ int wsum[8];
    __shared__ int idxs[T_TILE];

    // ---- Prologue 1: shuffle-based inclusive scan (1 barrier here). ----
    const int2* dur2 = (const int2*)(duration + b * SEQ);
    int2 d = dur2[tid];
    int sc = d.x + d.y;
    #pragma unroll
    for (int off = 1; off < 32; off <<= 1) {
        int v = __shfl_up_sync(0xffffffffu, sc, off);
        if (lane5 >= off) sc += v;
    }
    if (lane5 == 31) wsum[wid] = sc;
    __syncthreads();
    int wprefix = 0;
    #pragma unroll
    for (int w = 0; w < 8; w++)
        wprefix += (w < wid) ? wsum[w] : 0;
    int inc_hi = sc + wprefix;            // inclusive cumsum at elem 2*tid+1
    csum[2 * tid]     = inc_hi - d.y;
    csum[2 * tid + 1] = inc_hi;
    __syncthreads();

    // ---- Prologue 2: searchsorted(cumsum, pos, 'right'), clip to SEQ-1. ----
    if (tid < T_TILE) {
        int pos = t0 + tid;
        int lo = 0, hi = SEQ;
        while (lo < hi) {
            int mid = (lo + hi) >> 1;
            if (csum[mid] <= pos) lo = mid + 1; else hi = mid;
        }
        idxs[tid] = min(lo, SEQ - 1);
    }
    __syncthreads();

    // ---- Copy: 64 threads per row (64 float4 = 1KB contiguous),
    //      16 rows per thread in 4 groups of 4 (front-batched, MLP=4,
    //      only 16 float regs live per group -> fits the 32-reg cap). ----
    const float4* __restrict__ xb = (const float4*)x + (b * SEQ) * H4;
    float4* __restrict__ ob = (float4*)out + (b * TMEL + t0) * H4;
    const int lane = tid & 63;    // float4 index within row
    const int rsub = tid >> 6;    // 0..3

    #pragma unroll
    for (int g = 0; g < 4; g++) {
        int srcs[4];
        #pragma unroll
        for (int k = 0; k < 4; k++)
            srcs[k] = idxs[rsub + 4 * (g * 4 + k)];

        float4 v[4];
        #pragma unroll
        for (int k = 0; k < 4; k++)
            v[k] = __ldg(&xb[srcs[k] * H4 + lane]);

        #pragma unroll
        for (int k = 0; k < 4; k++) {
            int r = rsub + 4 * (g * 4 + k);
            if (t0 + r < TMEL)
                ob[r * H4 + lane] = v[k];
        }
    }

    // ---- mel_len appended after main output (if buffer includes it). ----
    if (blockIdx.x == 0 && tid == 255) {
        const int main_elems = BATCH * TMEL * HID;
        if (out_size >= main_elems + BATCH)
            out[main_elems + b] = (float)min(inc_hi, TMEL);
    }
}

extern "C" void kernel_launch(void* const* d_in, const int* in_sizes, int n_in,
                              void* d_out, int out_size) {
    const float* x        = (const float*)d_in[0];
    const int*   duration = (const int*)d_in[1];
    float*       out      = (float*)d_out;

    dim3 grid((TMEL + T_TILE - 1) / T_TILE, BATCH);  // (32, 32)
    length_regulator_kernel<<<grid, 256>>>(x, duration, out, out_size);
}

// round 7
// speedup vs baseline: 1.2737x; 1.0754x over previous
#include <cuda_runtime.h>

#define BATCH 32
#define SEQ   512
#define HID   256
#define TMEL  2000
#define H4    (HID / 4)      // 64 float4 per row
#define CHUNK 16             // input rows per CTA
#define NCHUNK (SEQ / CHUNK) // 32 CTAs per batch

__global__ __launch_bounds__(256, 6)
void length_regulator_kernel(const float* __restrict__ x,
                             const int* __restrict__ duration,
                             float* __restrict__ out,
                             int out_size) {
    const int b     = blockIdx.y;
    const int chunk = blockIdx.x;        // 0..31
    const int tid   = threadIdx.x;
    const int wid   = tid >> 5;
    const int lane5 = tid & 31;
    const int lane  = tid & 63;          // float4 slot within a row
    const int grp   = tid >> 6;          // 0..3 (row group)

    __shared__ int csum[SEQ];
    __shared__ int wsum[8];

    // ---- Front-batched loads: this group's 4 input rows (static addresses,
    //      independent of the scan -> latency hides under the prologue). ----
    const float4* __restrict__ xb = (const float4*)x + (b * SEQ) * H4;
    const int r0 = chunk * CHUNK + grp * 4;       // rows r0..r0+3
    float4 v[4];
    #pragma unroll
    for (int k = 0; k < 4; k++)
        v[k] = __ldg(&xb[(r0 + k) * H4 + lane]);

    // ---- Inclusive scan of all 512 durations (shuffle-based, 2 barriers). ----
    const int2* dur2 = (const int2*)(duration + b * SEQ);
    int2 d = dur2[tid];
    int sc = d.x + d.y;
    #pragma unroll
    for (int off = 1; off < 32; off <<= 1) {
        int t = __shfl_up_sync(0xffffffffu, sc, off);
        if (lane5 >= off) sc += t;
    }
    if (lane5 == 31) wsum[wid] = sc;
    __syncthreads();
    int wprefix = 0;
    #pragma unroll
    for (int w = 0; w < 8; w++)
        wprefix += (w < wid) ? wsum[w] : 0;
    int inc_hi = sc + wprefix;                    // cumsum at elem 2*tid+1
    csum[2 * tid]     = inc_hi - d.y;
    csum[2 * tid + 1] = inc_hi;
    __syncthreads();

    // ---- Input-driven expansion: row i covers output rows [csum[i-1], csum[i]).
    //      Each 64-thread group stores its 4 preloaded rows dur times. ----
    float4* __restrict__ ob = (float4*)out + (b * TMEL) * H4;
    #pragma unroll
    for (int k = 0; k < 4; k++) {
        int i  = r0 + k;
        int lo = (i == 0) ? 0 : csum[i - 1];
        int hi = csum[i];
        hi = min(hi, TMEL);
        for (int t = lo; t < hi; t++)             // 0..7 iterations, uniform in group
            ob[t * H4 + lane] = v[k];
    }

    // ---- Tail: positions [total, TMEL) replicate row SEQ-1. Spread across
    //      the 128 (chunk,grp) slots of this batch, stride 128. ----
    int total = csum[SEQ - 1];
    int tc = min(total, TMEL);
    int tstart = tc + chunk * 4 + grp;
    if (tstart < TMEL) {
        float4 vlast = __ldg(&xb[(SEQ - 1) * H4 + lane]);
        for (int t = tstart; t < TMEL; t += 4 * NCHUNK)
            ob[t * H4 + lane] = vlast;
    }

    // ---- mel_len appended after main output (if buffer includes it). ----
    if (chunk == 0 && tid == 0) {
        const int main_elems = BATCH * TMEL * HID;
        if (out_size >= main_elems + BATCH)
            out[main_elems + b] = (float)tc;
    }
}

extern "C" void kernel_launch(void* const* d_in, const int* in_sizes, int n_in,
                              void* d_out, int out_size) {
    const float* x        = (const float*)d_in[0];
    const int*   duration = (const int*)d_in[1];
    float*       out      = (float*)d_out;

    dim3 grid(NCHUNK, BATCH);   // (32, 32)
    length_regulator_kernel<<<grid, 256>>>(x, duration, out, out_size);
}